// round 6
// baseline (speedup 1.0000x reference)
#include <cuda_runtime.h>
#include <cstdint>

#define NUMEL        (8192 * 8192)            // 67,108,864
#define NGROUPS      (NUMEL / 4)              // 16,777,216 float4 groups
#define HALF_GROUPS  (NGROUPS / 2)            // codebook boundary
#define CB_ROWS      512                      // 2 codebooks * 256 centroids

#define TPB          512
#define WG_THREADS   128
#define NWG          (TPB / WG_THREADS)       // 4 warpgroups
#define JITER        2                        // groups per thread per tile
#define TILE_GROUPS  (TPB * JITER)            // 1024 groups = 16KB tile
#define WG_GROUPS    (WG_THREADS * JITER)     // 256 groups = 4KB per warpgroup
#define NTILES       (NGROUPS / TILE_GROUPS)  // 16384
#define GRID         (148 * 4)                // 592 persistent CTAs, 4/SM

__device__ __forceinline__ uint32_t smem_u32(const void* p) {
    uint32_t a;
    asm("{ .reg .u64 t; cvta.to.shared.u64 t, %1; cvt.u32.u64 %0, t; }"
        : "=r"(a) : "l"(p));
    return a;
}

__global__ __launch_bounds__(TPB, 4)          // 2048 thr/SM -> <=32 regs
void dequant_kernel(const float4* __restrict__ codebooks,   // 512 x float4 (8KB)
                    const float*  __restrict__ scales,      // NGROUPS/4 floats
                    const int*    __restrict__ codes,       // NGROUPS ints
                    float4*       __restrict__ out)         // NGROUPS float4
{
    __shared__ float4 scb[CB_ROWS];                 // 8KB codebook
    __shared__ float4 obuf[2][TILE_GROUPS];         // 2 x 16KB staging

    int t    = threadIdx.x;
    int gid  = t >> 7;          // warpgroup id 0..3
    int wtid = t & 127;         // lane within warpgroup
    int bar  = gid + 1;         // named barrier id (avoid 0)

    scb[t] = codebooks[t];      // 512 threads -> one row each
    __syncthreads();

    // Per-warpgroup region base within a tile (in groups).
    unsigned int wgoff = (unsigned)gid * WG_GROUPS;

    // ---- prologue: prefetch first tile's codes + scales ----
    unsigned int tile = blockIdx.x;
    int   c[JITER];
    float s[JITER];
    {
        unsigned int base = tile * TILE_GROUPS + wgoff;
        #pragma unroll
        for (int j = 0; j < JITER; j++)
            c[j] = __ldcs(&codes[base + (unsigned)j * WG_THREADS + wtid]);
        #pragma unroll
        for (int j = 0; j < JITER; j++)
            s[j] = __ldg(&scales[(base + (unsigned)j * WG_THREADS + wtid) >> 4]);
    }

    unsigned int it = 0;
    for (; tile < NTILES; tile += GRID, ++it) {
        int b = it & 1;
        unsigned int gbase = tile * TILE_GROUPS;
        // 1024-group tile never straddles the codebook-half boundary.
        const float4* cb = scb + ((gbase >= HALF_GROUPS) ? 256 : 0);

        // Gather + scale into registers (consumes prefetched c/s).
        float4 v[JITER];
        #pragma unroll
        for (int j = 0; j < JITER; j++) {
            float4 g = cb[c[j]];
            float sj = s[j];
            g.x *= sj; g.y *= sj; g.z *= sj; g.w *= sj;
            v[j] = g;
        }

        // Prefetch NEXT tile's codes/scales (overlaps barriers + TMA below).
        unsigned int ntile = tile + GRID;
        if (ntile < NTILES) {
            unsigned int nbase = ntile * TILE_GROUPS + wgoff;
            #pragma unroll
            for (int j = 0; j < JITER; j++)
                c[j] = __ldcs(&codes[nbase + (unsigned)j * WG_THREADS + wtid]);
            #pragma unroll
            for (int j = 0; j < JITER; j++)
                s[j] = __ldg(&scales[(nbase + (unsigned)j * WG_THREADS + wtid) >> 4]);
        }

        // Reclaim this warpgroup's quarter of buffer b: our bulk store from
        // 2 tiles ago must have finished reading smem.
        if (it >= 2 && wtid == 0)
            asm volatile("cp.async.bulk.wait_group.read 1;" ::: "memory");
        asm volatile("bar.sync %0, %1;" :: "r"(bar), "r"(WG_THREADS) : "memory");

        // Conflict-free STS.128 into our contiguous 4KB chunk.
        float4* dst = &obuf[b][wgoff];
        #pragma unroll
        for (int j = 0; j < JITER; j++)
            dst[j * WG_THREADS + wtid] = v[j];
        asm volatile("bar.sync %0, %1;" :: "r"(bar), "r"(WG_THREADS) : "memory");

        // Warpgroup leader hands its 4KB chunk to the TMA engine.
        if (wtid == 0) {
            asm volatile("fence.proxy.async.shared::cta;" ::: "memory");
            uint32_t saddr = smem_u32(&obuf[b][wgoff]);
            const float4* gdst = out + gbase + wgoff;
            asm volatile(
                "cp.async.bulk.global.shared::cta.bulk_group [%0], [%1], %2;"
                :: "l"(gdst), "r"(saddr), "r"((int)(WG_GROUPS * 16)) : "memory");
            asm volatile("cp.async.bulk.commit_group;" ::: "memory");
        }
    }

    // Drain all outstanding bulk stores before exit.
    if (wtid == 0)
        asm volatile("cp.async.bulk.wait_group 0;" ::: "memory");
}

extern "C" void kernel_launch(void* const* d_in, const int* in_sizes, int n_in,
                              void* d_out, int out_size)
{
    const float4* codebooks = (const float4*)d_in[0];  // [2,256,4] fp32
    const float*  scales    = (const float*) d_in[1];  // [numel/64, 1] fp32
    const int*    codes     = (const int*)   d_in[2];  // [2, numel/8] int32 flat
    float4*       out       = (float4*)d_out;          // [8192, 8192] fp32

    dequant_kernel<<<GRID, TPB>>>(codebooks, scales, codes, out);
}

// round 7
// speedup vs baseline: 1.0603x; 1.0603x over previous
#include <cuda_runtime.h>
#include <cstdint>

#define NUMEL        (8192 * 8192)            // 67,108,864
#define NGROUPS      (NUMEL / 4)              // 16,777,216 float4 groups
#define HALF_GROUPS  (NGROUPS / 2)            // codebook boundary
#define CB_ROWS      512                      // 2 codebooks * 256 centroids

#define TPB          512
#define JITER        2                        // groups per thread per tile
#define TILE_GROUPS  (TPB * JITER)            // 1024 groups = 16KB tile
#define TILE_BYTES   (TILE_GROUPS * 16)       // 16384
#define NTILES       (NGROUPS / TILE_GROUPS)  // 16384
#define NBUF         3                        // 3-deep store pipeline
#define GRID         (148 * 4)                // 592 persistent CTAs, 4/SM

__device__ __forceinline__ uint32_t smem_u32(const void* p) {
    uint32_t a;
    asm("{ .reg .u64 t; cvta.to.shared.u64 t, %1; cvt.u32.u64 %0, t; }"
        : "=r"(a) : "l"(p));
    return a;
}

__global__ __launch_bounds__(TPB, 4)          // 2048 thr/SM -> <=32 regs
void dequant_kernel(const float4* __restrict__ codebooks,   // 512 x float4 (8KB)
                    const float*  __restrict__ scales,      // NGROUPS/4 floats
                    const int*    __restrict__ codes,       // NGROUPS ints
                    float4*       __restrict__ out)         // NGROUPS float4
{
    __shared__ float4 scb[CB_ROWS];                 // 8KB codebook
    __shared__ float4 obuf[NBUF][TILE_GROUPS];      // 3 x 16KB staging

    int t = threadIdx.x;
    scb[t] = codebooks[t];      // 512 threads -> one row each
    __syncthreads();

    // ---- prologue: prefetch first tile's codes + scales ----
    unsigned int tile = blockIdx.x;
    int   c[JITER];
    float s[JITER];
    {
        unsigned int gbase = tile * TILE_GROUPS;
        #pragma unroll
        for (int j = 0; j < JITER; j++)
            c[j] = __ldcs(&codes[gbase + (unsigned)j * TPB + t]);
        #pragma unroll
        for (int j = 0; j < JITER; j++)
            s[j] = __ldg(&scales[(gbase + (unsigned)j * TPB + t) >> 4]);
    }

    unsigned int it = 0;
    int b = 0;                                  // rotating buffer index
    for (; tile < NTILES; tile += GRID, ++it) {
        unsigned int gbase = tile * TILE_GROUPS;
        // 1024-group tile never straddles the codebook-half boundary.
        const float4* cb = scb + ((gbase >= HALF_GROUPS) ? 256 : 0);

        // Gather + scale into registers (consumes prefetched c/s).
        float4 v[JITER];
        #pragma unroll
        for (int j = 0; j < JITER; j++) {
            float4 g = cb[c[j]];
            float sj = s[j];
            g.x *= sj; g.y *= sj; g.z *= sj; g.w *= sj;
            v[j] = g;
        }

        // Prefetch NEXT tile's codes/scales (overlaps barriers + TMA below).
        unsigned int ntile = tile + GRID;
        if (ntile < NTILES) {
            unsigned int nbase = ntile * TILE_GROUPS;
            #pragma unroll
            for (int j = 0; j < JITER; j++)
                c[j] = __ldcs(&codes[nbase + (unsigned)j * TPB + t]);
            #pragma unroll
            for (int j = 0; j < JITER; j++)
                s[j] = __ldg(&scales[(nbase + (unsigned)j * TPB + t) >> 4]);
        }

        // Reclaim buffer b: the bulk store issued NBUF tiles ago must have
        // finished READING smem (allow NBUF-1 = 2 still in flight).
        if (it >= NBUF && t == 0)
            asm volatile("cp.async.bulk.wait_group.read 2;" ::: "memory");
        __syncthreads();

        // Conflict-free STS.128 (linear 16B per lane).
        #pragma unroll
        for (int j = 0; j < JITER; j++)
            obuf[b][j * TPB + t] = v[j];
        __syncthreads();

        // Hand the 16KB tile to the TMA engine.
        if (t == 0) {
            asm volatile("fence.proxy.async.shared::cta;" ::: "memory");
            uint32_t saddr = smem_u32(&obuf[b][0]);
            const float4* gdst = out + gbase;
            asm volatile(
                "cp.async.bulk.global.shared::cta.bulk_group [%0], [%1], %2;"
                :: "l"(gdst), "r"(saddr), "r"((int)TILE_BYTES) : "memory");
            asm volatile("cp.async.bulk.commit_group;" ::: "memory");
        }

        b = (b + 1 == NBUF) ? 0 : b + 1;
    }

    // Drain all outstanding bulk stores before exit.
    if (t == 0)
        asm volatile("cp.async.bulk.wait_group 0;" ::: "memory");
}

extern "C" void kernel_launch(void* const* d_in, const int* in_sizes, int n_in,
                              void* d_out, int out_size)
{
    const float4* codebooks = (const float4*)d_in[0];  // [2,256,4] fp32
    const float*  scales    = (const float*) d_in[1];  // [numel/64, 1] fp32
    const int*    codes     = (const int*)   d_in[2];  // [2, numel/8] int32 flat
    float4*       out       = (float4*)d_out;          // [8192, 8192] fp32

    dequant_kernel<<<GRID, TPB>>>(codebooks, scales, codes, out);
}